// round 1
// baseline (speedup 1.0000x reference)
#include <cuda_runtime.h>
#include <cuda_bf16.h>
#include <cstdint>

#define N_NODES 20000
#define N_EDGES 200000
#define FEAT    128
#define NB      8
#define SI      16
#define SO      16
#define NREL    230
#define WROW    (NB*SI*SO)   // 2048 floats per relation
#define CHUNK   64           // edges per block in edge kernel

// ---------------- scratch (device globals; no allocation allowed) ------------
__device__ float g_agg[(size_t)N_NODES * FEAT];      // 10.24 MB
__device__ int   g_counts[NREL];
__device__ int   g_cursor[NREL];
__device__ int   g_perm[N_EDGES];

// ---------------- K0: zero agg + counters ------------------------------------
__global__ void zero_kernel() {
    size_t i = (size_t)blockIdx.x * blockDim.x + threadIdx.x;
    const size_t n4 = (size_t)N_NODES * FEAT / 4;
    float4 z = make_float4(0.f, 0.f, 0.f, 0.f);
    if (i < n4) reinterpret_cast<float4*>(g_agg)[i] = z;
    if (blockIdx.x == 0 && threadIdx.x < NREL) g_counts[threadIdx.x] = 0;
}

// ---------------- K1: histogram of edge types --------------------------------
__global__ void hist_kernel(const int* __restrict__ etype) {
    int e = blockIdx.x * blockDim.x + threadIdx.x;
    if (e < N_EDGES) atomicAdd(&g_counts[etype[e]], 1);
}

// ---------------- K2: exclusive scan (single block, 256 threads) -------------
__global__ void scan_kernel() {
    __shared__ int s[256];
    int t = threadIdx.x;
    int c = (t < NREL) ? g_counts[t] : 0;
    s[t] = c;
    __syncthreads();
    #pragma unroll
    for (int off = 1; off < 256; off <<= 1) {
        int v = (t >= off) ? s[t - off] : 0;
        __syncthreads();
        s[t] += v;
        __syncthreads();
    }
    if (t < NREL) g_cursor[t] = s[t] - c;   // exclusive prefix = start offset
}

// ---------------- K3: scatter edge ids grouped by type -----------------------
__global__ void scatter_kernel(const int* __restrict__ etype) {
    int e = blockIdx.x * blockDim.x + threadIdx.x;
    if (e < N_EDGES) {
        int t = etype[e];
        int pos = atomicAdd(&g_cursor[t], 1);
        g_perm[pos] = e;
    }
}

// ---------------- K4: edge message + scatter-add ------------------------------
// 128 threads = 128 output channels. thread o: block b=o>>4, col oo=o&15.
// Weights for current relation cached in 16 registers per thread.
__global__ void __launch_bounds__(128) edge_kernel(
    const float* __restrict__ h,
    const float* __restrict__ weight,
    const float* __restrict__ enorm,
    const int*   __restrict__ esrc,
    const int*   __restrict__ edst,
    const int*   __restrict__ etype)
{
    const int o  = threadIdx.x;
    const int b  = o >> 4;
    const int oo = o & 15;

    int e0 = blockIdx.x * CHUNK;
    int e1 = e0 + CHUNK;
    if (e1 > N_EDGES) e1 = N_EDGES;

    float w[16];
    int cur = -1;

    for (int ei = e0; ei < e1; ++ei) {
        int e = __ldg(&g_perm[ei]);
        int t = __ldg(&etype[e]);
        if (t != cur) {
            cur = t;
            const float* wp = weight + (size_t)t * WROW + b * (SI * SO) + oo;
            #pragma unroll
            for (int i = 0; i < 16; ++i) w[i] = __ldg(wp + i * SO);
        }
        int   s  = __ldg(&esrc[e]);
        int   d  = __ldg(&edst[e]);
        float en = __ldg(&enorm[e]);

        const float4* sp = reinterpret_cast<const float4*>(h + (size_t)s * FEAT + b * SI);
        float4 v0 = __ldg(sp + 0);
        float4 v1 = __ldg(sp + 1);
        float4 v2 = __ldg(sp + 2);
        float4 v3 = __ldg(sp + 3);

        float acc =
            v0.x * w[0]  + v0.y * w[1]  + v0.z * w[2]  + v0.w * w[3]  +
            v1.x * w[4]  + v1.y * w[5]  + v1.z * w[6]  + v1.w * w[7]  +
            v2.x * w[8]  + v2.y * w[9]  + v2.z * w[10] + v2.w * w[11] +
            v3.x * w[12] + v3.y * w[13] + v3.z * w[14] + v3.w * w[15];

        atomicAdd(&g_agg[(size_t)d * FEAT + o], acc * en);
    }
}

// ---------------- K5: self-loop GEMM + epilogue + time-embedding -------------
// Tile: 64 nodes x 128 outs. 256 threads, thread = (tm = tid>>5, to = tid&31),
// computes 8 nodes x 4 outs. K-chunked smem tiles (KT=32).
#define MT 64
#define KT 32
__global__ void __launch_bounds__(256) final_kernel(
    const float* __restrict__ h,
    const float* __restrict__ node_norm,
    const float* __restrict__ h_bias,
    const float* __restrict__ loop_weight,
    const float* __restrict__ time_embed,
    const int*   __restrict__ time_idx,
    float*       __restrict__ out)
{
    __shared__ float sW[KT][FEAT];       // 16 KB
    __shared__ float sH[MT][KT + 1];     // ~8.25 KB

    const int tid = threadIdx.x;
    const int tm  = tid >> 5;
    const int to  = tid & 31;
    const int n0  = blockIdx.x * MT;

    float acc[8][4];
    #pragma unroll
    for (int r = 0; r < 8; ++r)
        #pragma unroll
        for (int c = 0; c < 4; ++c) acc[r][c] = 0.f;

    for (int kt = 0; kt < FEAT / KT; ++kt) {
        // load W tile: KT x 128 = 4096 floats = 1024 float4 (4 per thread)
        #pragma unroll
        for (int j = 0; j < 4; ++j) {
            int idx = tid + j * 256;
            int r   = idx >> 5;       // 0..31
            int c4  = idx & 31;       // 0..31
            float4 v = __ldg(reinterpret_cast<const float4*>(
                loop_weight + (size_t)(kt * KT + r) * FEAT + c4 * 4));
            *reinterpret_cast<float4*>(&sW[r][c4 * 4]) = v;
        }
        // load H tile: 64 x 32 = 2048 floats = 512 float4 (2 per thread)
        #pragma unroll
        for (int j = 0; j < 2; ++j) {
            int idx = tid + j * 256;
            int r   = idx >> 3;       // 0..63
            int c4  = idx & 7;        // 0..7
            int n   = n0 + r;
            float4 v = make_float4(0.f, 0.f, 0.f, 0.f);
            if (n < N_NODES)
                v = __ldg(reinterpret_cast<const float4*>(
                        h + (size_t)n * FEAT + kt * KT + c4 * 4));
            sH[r][c4 * 4 + 0] = v.x;
            sH[r][c4 * 4 + 1] = v.y;
            sH[r][c4 * 4 + 2] = v.z;
            sH[r][c4 * 4 + 3] = v.w;
        }
        __syncthreads();

        #pragma unroll
        for (int k = 0; k < KT; ++k) {
            float4 w = *reinterpret_cast<const float4*>(&sW[k][to * 4]);
            #pragma unroll
            for (int r = 0; r < 8; ++r) {
                float hv = sH[tm * 8 + r][k];
                acc[r][0] += hv * w.x;
                acc[r][1] += hv * w.y;
                acc[r][2] += hv * w.z;
                acc[r][3] += hv * w.w;
            }
        }
        __syncthreads();
    }

    // epilogue: relu(agg*node_norm + h_bias + loop_message)
    const int o0 = to * 4;
    float4 hb = __ldg(reinterpret_cast<const float4*>(h_bias + o0));
    #pragma unroll
    for (int r = 0; r < 8; ++r) {
        int n = n0 + tm * 8 + r;
        if (n < N_NODES) {
            float nn = __ldg(&node_norm[n]);
            float4 ag = *reinterpret_cast<const float4*>(&g_agg[(size_t)n * FEAT + o0]);
            float4 res;
            res.x = fmaxf(acc[r][0] + ag.x * nn + hb.x, 0.f);
            res.y = fmaxf(acc[r][1] + ag.y * nn + hb.y, 0.f);
            res.z = fmaxf(acc[r][2] + ag.z * nn + hb.z, 0.f);
            res.w = fmaxf(acc[r][3] + ag.w * nn + hb.w, 0.f);
            *reinterpret_cast<float4*>(out + (size_t)n * FEAT + o0) = res;
        }
    }

    // time embedding gather: out2[n, :] = time_embed[time_idx[n], :]
    float* out2 = out + (size_t)N_NODES * FEAT;
    #pragma unroll
    for (int j = 0; j < 8; ++j) {
        int idx = tid + j * 256;      // covers 2048 float4 = 64 rows x 32 f4
        int r   = idx >> 5;
        int c4  = idx & 31;
        int n   = n0 + r;
        if (n < N_NODES) {
            int ti = __ldg(&time_idx[n]);
            float4 v = __ldg(reinterpret_cast<const float4*>(
                time_embed + (size_t)ti * FEAT + c4 * 4));
            *reinterpret_cast<float4*>(out2 + (size_t)n * FEAT + c4 * 4) = v;
        }
    }
}

// ---------------- launch ------------------------------------------------------
extern "C" void kernel_launch(void* const* d_in, const int* in_sizes, int n_in,
                              void* d_out, int out_size) {
    const float* h           = (const float*)d_in[0];
    const float* edge_norm   = (const float*)d_in[1];
    const float* node_norm   = (const float*)d_in[2];
    const float* weight      = (const float*)d_in[3];
    const float* h_bias      = (const float*)d_in[4];
    const float* loop_weight = (const float*)d_in[5];
    const float* time_embed  = (const float*)d_in[6];
    const int*   edge_src    = (const int*)d_in[7];
    const int*   edge_dst    = (const int*)d_in[8];
    const int*   edge_type   = (const int*)d_in[9];
    const int*   time_idx    = (const int*)d_in[10];
    float* out = (float*)d_out;

    // K0: zero agg + counters
    {
        int n4 = N_NODES * FEAT / 4;
        zero_kernel<<<(n4 + 255) / 256, 256>>>();
    }
    // K1: histogram
    hist_kernel<<<(N_EDGES + 255) / 256, 256>>>(edge_type);
    // K2: scan -> cursor = start offsets
    scan_kernel<<<1, 256>>>();
    // K3: scatter -> perm sorted by type
    scatter_kernel<<<(N_EDGES + 255) / 256, 256>>>(edge_type);
    // K4: edge messages + atomic aggregation
    edge_kernel<<<(N_EDGES + CHUNK - 1) / CHUNK, 128>>>(
        h, weight, edge_norm, edge_src, edge_dst, edge_type);
    // K5: self-loop GEMM + epilogue + time embedding
    final_kernel<<<(N_NODES + MT - 1) / MT, 256>>>(
        h, node_norm, h_bias, loop_weight, time_embed, time_idx, out);
}

// round 2
// speedup vs baseline: 2.6979x; 2.6979x over previous
#include <cuda_runtime.h>
#include <cuda_bf16.h>
#include <cstdint>

#define N_NODES 20000
#define N_EDGES 200000
#define FEAT    128
#define NB      8
#define SI      16
#define SO      16
#define NREL    230
#define WROW    (NB*SI*SO)       // 2048 floats per relation
#define NSUB    32               // sub-counters per relation (contention spreading)
#define NCNT    (NREL*NSUB)      // 7360
#define EPW     32               // edges per warp in edge kernel

// ---------------- packed f32x2 helpers (Blackwell sm_103a) --------------------
#define PACK_F32X2(out, lo, hi) \
    asm("mov.b64 %0, {%1, %2};" : "=l"(out) : "f"(lo), "f"(hi))
#define UNPACK_F32X2(lo, hi, in) \
    asm("mov.b64 {%0, %1}, %2;" : "=f"(lo), "=f"(hi) : "l"(in))
#define FMA_F32X2(d, a, b, c) \
    asm("fma.rn.f32x2 %0, %1, %2, %3;" : "=l"(d) : "l"(a), "l"(b), "l"(c))

// ---------------- scratch (device globals; no allocation allowed) -------------
__device__ float g_agg[(size_t)N_NODES * FEAT];      // 10.24 MB
__device__ int   g_counts[NCNT];
__device__ int   g_cursor[NCNT];
__device__ int4  g_edge[N_EDGES];                    // sorted records {src,dst,type,norm}

// ---------------- K0: zero agg + counters -------------------------------------
__global__ void zero_kernel() {
    int i = blockIdx.x * blockDim.x + threadIdx.x;
    const int n4 = N_NODES * FEAT / 4;   // 640000
    if (i < n4) reinterpret_cast<float4*>(g_agg)[i] =
        make_float4(0.f, 0.f, 0.f, 0.f);
    if (i < NCNT) g_counts[i] = 0;
}

// ---------------- K1: histogram over split counters ---------------------------
__global__ void hist_kernel(const int* __restrict__ etype) {
    int e = blockIdx.x * blockDim.x + threadIdx.x;
    if (e < N_EDGES) {
        int t = etype[e];
        atomicAdd(&g_counts[t * NSUB + (e & (NSUB - 1))], 1);   // RED (no return)
    }
}

// ---------------- K2: exclusive scan over 7360 counters (1 block, 1024 thr) ---
__global__ void __launch_bounds__(1024) scan_kernel() {
    __shared__ int sp[1024];
    int t = threadIdx.x;
    int base = t * 8;
    int v[8];
    int sum = 0;
    #pragma unroll
    for (int i = 0; i < 8; ++i) {
        v[i] = (base + i < NCNT) ? g_counts[base + i] : 0;
        sum += v[i];
    }
    sp[t] = sum;
    __syncthreads();
    #pragma unroll
    for (int off = 1; off < 1024; off <<= 1) {
        int x = (t >= off) ? sp[t - off] : 0;
        __syncthreads();
        sp[t] += x;
        __syncthreads();
    }
    int run = sp[t] - sum;       // exclusive prefix of this thread's chunk
    #pragma unroll
    for (int i = 0; i < 8; ++i) {
        if (base + i < NCNT) g_cursor[base + i] = run;
        run += v[i];
    }
}

// ---------------- K3: scatter packed edge records grouped by type -------------
__global__ void scatter_kernel(const int* __restrict__ etype,
                               const int* __restrict__ esrc,
                               const int* __restrict__ edst,
                               const float* __restrict__ enorm) {
    int e = blockIdx.x * blockDim.x + threadIdx.x;
    if (e < N_EDGES) {
        int t = etype[e];
        int c = t * NSUB + (e & (NSUB - 1));
        int pos = atomicAdd(&g_cursor[c], 1);
        g_edge[pos] = make_int4(esrc[e], edst[e], t, __float_as_int(enorm[e]));
    }
}

// ---------------- K4: edge message + vector scatter-add ------------------------
// warp per edge-chunk; lane handles 4 consecutive output channels (lane*4..+3).
// block b = lane>>2, quad q = lane&3. Weights register-cached, packed f32x2.
__global__ void __launch_bounds__(256) edge_kernel(
    const float* __restrict__ h,
    const float* __restrict__ weight)
{
    const int warp = blockIdx.x * 8 + (threadIdx.x >> 5);
    const int lane = threadIdx.x & 31;
    int e0 = warp * EPW;
    if (e0 >= N_EDGES) return;
    int e1 = e0 + EPW;
    if (e1 > N_EDGES) e1 = N_EDGES;

    const int b = lane >> 2;
    const int q = lane & 3;

    unsigned long long w01[16], w23[16];
    int cur = -1;

    for (int e = e0; e < e1; ++e) {
        int4 rec = __ldg(&g_edge[e]);            // broadcast across warp
        if (rec.z != cur) {
            cur = rec.z;
            const float4* wp = reinterpret_cast<const float4*>(
                weight + (size_t)cur * WROW + b * (SI * SO)) + q;
            #pragma unroll
            for (int i = 0; i < 16; ++i) {
                float4 v = __ldg(wp + i * 4);    // W[b][i][q*4..q*4+3]
                PACK_F32X2(w01[i], v.x, v.y);
                PACK_F32X2(w23[i], v.z, v.w);
            }
        }
        const float4* sp = reinterpret_cast<const float4*>(
            h + (size_t)rec.x * FEAT + b * SI);
        float4 s0 = __ldg(sp + 0);
        float4 s1 = __ldg(sp + 1);
        float4 s2 = __ldg(sp + 2);
        float4 s3 = __ldg(sp + 3);

        unsigned long long a01 = 0ULL, a23 = 0ULL;   // (0.f, 0.f)
        #define EK_STEP(i, val) { unsigned long long _p;            \
            PACK_F32X2(_p, val, val);                                \
            FMA_F32X2(a01, _p, w01[i], a01);                         \
            FMA_F32X2(a23, _p, w23[i], a23); }
        EK_STEP(0,  s0.x) EK_STEP(1,  s0.y) EK_STEP(2,  s0.z) EK_STEP(3,  s0.w)
        EK_STEP(4,  s1.x) EK_STEP(5,  s1.y) EK_STEP(6,  s1.z) EK_STEP(7,  s1.w)
        EK_STEP(8,  s2.x) EK_STEP(9,  s2.y) EK_STEP(10, s2.z) EK_STEP(11, s2.w)
        EK_STEP(12, s3.x) EK_STEP(13, s3.y) EK_STEP(14, s3.z) EK_STEP(15, s3.w)
        #undef EK_STEP

        float en = __int_as_float(rec.w);
        float r0, r1, r2, r3;
        UNPACK_F32X2(r0, r1, a01);
        UNPACK_F32X2(r2, r3, a23);
        r0 *= en; r1 *= en; r2 *= en; r3 *= en;

        float* dst = g_agg + (size_t)rec.y * FEAT + lane * 4;
        asm volatile("red.global.add.v4.f32 [%0], {%1, %2, %3, %4};"
                     :: "l"(dst), "f"(r0), "f"(r1), "f"(r2), "f"(r3)
                     : "memory");
    }
}

// ---------------- K5: self-loop GEMM + epilogue + time-embedding --------------
// Tile 64 nodes x 128 outs, 256 threads, thread computes 8x4 with f32x2 FMA.
#define MT 64
#define KT 32
__global__ void __launch_bounds__(256) final_kernel(
    const float* __restrict__ h,
    const float* __restrict__ node_norm,
    const float* __restrict__ h_bias,
    const float* __restrict__ loop_weight,
    const float* __restrict__ time_embed,
    const int*   __restrict__ time_idx,
    float*       __restrict__ out)
{
    __shared__ float sW[KT][FEAT];       // 16 KB
    __shared__ float sH[MT][KT + 1];     // ~8.25 KB

    const int tid = threadIdx.x;
    const int tm  = tid >> 5;
    const int to  = tid & 31;
    const int n0  = blockIdx.x * MT;

    unsigned long long acc01[8], acc23[8];
    #pragma unroll
    for (int r = 0; r < 8; ++r) { acc01[r] = 0ULL; acc23[r] = 0ULL; }

    for (int kt = 0; kt < FEAT / KT; ++kt) {
        #pragma unroll
        for (int j = 0; j < 4; ++j) {
            int idx = tid + j * 256;
            int r   = idx >> 5;
            int c4  = idx & 31;
            float4 v = __ldg(reinterpret_cast<const float4*>(
                loop_weight + (size_t)(kt * KT + r) * FEAT + c4 * 4));
            *reinterpret_cast<float4*>(&sW[r][c4 * 4]) = v;
        }
        #pragma unroll
        for (int j = 0; j < 2; ++j) {
            int idx = tid + j * 256;
            int r   = idx >> 3;
            int c4  = idx & 7;
            int n   = n0 + r;
            float4 v = make_float4(0.f, 0.f, 0.f, 0.f);
            if (n < N_NODES)
                v = __ldg(reinterpret_cast<const float4*>(
                        h + (size_t)n * FEAT + kt * KT + c4 * 4));
            sH[r][c4 * 4 + 0] = v.x;
            sH[r][c4 * 4 + 1] = v.y;
            sH[r][c4 * 4 + 2] = v.z;
            sH[r][c4 * 4 + 3] = v.w;
        }
        __syncthreads();

        #pragma unroll
        for (int k = 0; k < KT; ++k) {
            float4 wv = *reinterpret_cast<const float4*>(&sW[k][to * 4]);
            unsigned long long w01, w23;
            PACK_F32X2(w01, wv.x, wv.y);
            PACK_F32X2(w23, wv.z, wv.w);
            #pragma unroll
            for (int r = 0; r < 8; ++r) {
                float hv = sH[tm * 8 + r][k];
                unsigned long long h2;
                PACK_F32X2(h2, hv, hv);
                FMA_F32X2(acc01[r], h2, w01, acc01[r]);
                FMA_F32X2(acc23[r], h2, w23, acc23[r]);
            }
        }
        __syncthreads();
    }

    // epilogue: relu(agg*node_norm + h_bias + loop_message)
    const int o0 = to * 4;
    float4 hb = __ldg(reinterpret_cast<const float4*>(h_bias + o0));
    #pragma unroll
    for (int r = 0; r < 8; ++r) {
        int n = n0 + tm * 8 + r;
        if (n < N_NODES) {
            float nn = __ldg(&node_norm[n]);
            float4 ag = *reinterpret_cast<const float4*>(&g_agg[(size_t)n * FEAT + o0]);
            float a0, a1, a2, a3;
            UNPACK_F32X2(a0, a1, acc01[r]);
            UNPACK_F32X2(a2, a3, acc23[r]);
            float4 res;
            res.x = fmaxf(a0 + ag.x * nn + hb.x, 0.f);
            res.y = fmaxf(a1 + ag.y * nn + hb.y, 0.f);
            res.z = fmaxf(a2 + ag.z * nn + hb.z, 0.f);
            res.w = fmaxf(a3 + ag.w * nn + hb.w, 0.f);
            *reinterpret_cast<float4*>(out + (size_t)n * FEAT + o0) = res;
        }
    }

    // time embedding gather
    float* out2 = out + (size_t)N_NODES * FEAT;
    #pragma unroll
    for (int j = 0; j < 8; ++j) {
        int idx = tid + j * 256;
        int r   = idx >> 5;
        int c4  = idx & 31;
        int n   = n0 + r;
        if (n < N_NODES) {
            int ti = __ldg(&time_idx[n]);
            float4 v = __ldg(reinterpret_cast<const float4*>(
                time_embed + (size_t)ti * FEAT + c4 * 4));
            *reinterpret_cast<float4*>(out2 + (size_t)n * FEAT + c4 * 4) = v;
        }
    }
}

// ---------------- launch -------------------------------------------------------
extern "C" void kernel_launch(void* const* d_in, const int* in_sizes, int n_in,
                              void* d_out, int out_size) {
    const float* h           = (const float*)d_in[0];
    const float* edge_norm   = (const float*)d_in[1];
    const float* node_norm   = (const float*)d_in[2];
    const float* weight      = (const float*)d_in[3];
    const float* h_bias      = (const float*)d_in[4];
    const float* loop_weight = (const float*)d_in[5];
    const float* time_embed  = (const float*)d_in[6];
    const int*   edge_src    = (const int*)d_in[7];
    const int*   edge_dst    = (const int*)d_in[8];
    const int*   edge_type   = (const int*)d_in[9];
    const int*   time_idx    = (const int*)d_in[10];
    float* out = (float*)d_out;

    {
        int n4 = N_NODES * FEAT / 4;     // 640000 (> NCNT)
        zero_kernel<<<(n4 + 255) / 256, 256>>>();
    }
    hist_kernel<<<(N_EDGES + 255) / 256, 256>>>(edge_type);
    scan_kernel<<<1, 1024>>>();
    scatter_kernel<<<(N_EDGES + 255) / 256, 256>>>(edge_type, edge_src,
                                                   edge_dst, edge_norm);
    {
        int warps = (N_EDGES + EPW - 1) / EPW;      // 6250
        int ctas  = (warps + 7) / 8;                // 782
        edge_kernel<<<ctas, 256>>>(h, weight);
    }
    final_kernel<<<(N_NODES + MT - 1) / MT, 256>>>(
        h, node_norm, h_bias, loop_weight, time_embed, time_idx, out);
}